// round 14
// baseline (speedup 1.0000x reference)
#include <cuda_runtime.h>
#include <math.h>

// Problem constants (B=4, S=4096, D=2048, E=8, K=2)
#define NTOK    16384
#define DIM     2048
#define NEXP    8
#define NASSIGN (NTOK*2)       // 32768
#define CAP     5120           // int(NTOK*2/8 * 1.25)
#define NTASK   (NTOK/4)       // 4096 tasks of 4 tokens
#define NBLK    152            // persistent, 1 block per SM
#define THREADS 512            // 16 warps
#define RING    4
#define ROWB    512            // bytes per row per chunk (128 dims)
#define STAGEB  (4*ROWB)       // 2 KB per warp-stage (4 rows)
#define RINGB   (RING*STAGEB)  // 8 KB per warp
#define W_BYTES (NEXP*DIM*4)   // 64 KB
#define SMEM_DYN (W_BYTES + 16*RINGB)   // 192 KB

// Output layout (float32): [0,32768) indices | [32768,65536) weights |
// [65536] loss | [65537,98305) mask

__device__ int      g_cnt[NEXP];
__device__ float    g_probsum[NEXP];
__device__ unsigned g_done;
__device__ unsigned g_ticket;
__device__ unsigned long long g_bucket[NEXP][NASSIGN];

__device__ __forceinline__ void ffma2(unsigned long long& d,
                                      unsigned long long a,
                                      unsigned long long b) {
    asm("fma.rn.f32x2 %0, %1, %2, %0;" : "+l"(d) : "l"(a), "l"(b));
}
__device__ __forceinline__ float unpack_sum(unsigned long long v) {
    unsigned lo, hi;
    asm("mov.b64 {%0, %1}, %2;" : "=r"(lo), "=r"(hi) : "l"(v));
    return __uint_as_float(lo) + __uint_as_float(hi);
}
__device__ __forceinline__ unsigned smem_u32(const void* p) {
    return (unsigned)__cvta_generic_to_shared(p);
}
// cp.async.cg: 16B gmem->smem, bypasses L1, zero register cost.
// "memory" clobber keeps preceding LDS emitted BEFORE the overwrite issue.
__device__ __forceinline__ void cp_async16(unsigned dst, const void* src) {
    asm volatile("cp.async.cg.shared.global [%0], [%1], 16;"
                 :: "r"(dst), "l"(src) : "memory");
}
__device__ __forceinline__ void cp_commit() {
    asm volatile("cp.async.commit_group;" ::: "memory");
}
template <int N>
__device__ __forceinline__ void cp_wait() {
    asm volatile("cp.async.wait_group %0;" :: "n"(N) : "memory");
}
__device__ __forceinline__ int grab_task(int lane) {
    int t = 0;
    if (lane == 0) t = (int)atomicAdd(&g_ticket, 1u);
    return __shfl_sync(0xffffffffu, t, 0);
}

// Persistent fused kernel. Each warp pulls 4-token tasks; x flows through a
// per-warp 4-deep cp.async ring (no block barriers in the hot loop; each lane
// consumes only the 16B it copied). LAST arriving block computes loss +
// (rare) capacity drop + resets scratch for the next graph replay.
__global__ __launch_bounds__(THREADS, 1)
void router_main(const float* __restrict__ x,
                 const float* __restrict__ wg,
                 float* __restrict__ out) {
    extern __shared__ float sw[];           // w: 64 KB, rings after
    __shared__ float s_prob[NEXP];
    __shared__ int   s_last;

    const int tid  = threadIdx.x;
    const int warp = tid >> 5;
    const int lane = tid & 31;
    if (tid < NEXP) s_prob[tid] = 0.0f;

    // stage w_gate into shared ONCE per persistent block
    {
        float4* sw4 = (float4*)sw;
        const float4* wg4 = (const float4*)wg;
        #pragma unroll
        for (int i = tid; i < NEXP * DIM / 4; i += THREADS) sw4[i] = wg4[i];
    }
    __syncthreads();
    const ulonglong2* sw2 = (const ulonglong2*)sw;

    char* ring = (char*)sw + W_BYTES + warp * RINGB;
    const unsigned ring_u = smem_u32(ring) + lane * 16;
    const unsigned lane16 = lane * 16;

    int task = grab_task(lane);
    while (task < NTASK) {
        const char* xg = (const char*)x + (size_t)(task * 4) * (DIM * 4);

        // prefill chunks 0..3 (group g <-> chunk g)
        #pragma unroll
        for (int s = 0; s < RING; s++) {
            #pragma unroll
            for (int r = 0; r < 4; r++)
                cp_async16(ring_u + s * STAGEB + r * ROWB,
                           xg + (size_t)r * (DIM * 4) + s * ROWB + lane16);
            cp_commit();
        }

        int next = grab_task(lane);   // ATOMG latency hidden under pipeline

        unsigned long long acc[4][NEXP];
        #pragma unroll
        for (int t = 0; t < 4; t++)
            #pragma unroll
            for (int e = 0; e < NEXP; e++) acc[t][e] = 0ull;

        #pragma unroll
        for (int c = 0; c < 16; c++) {
            cp_wait<RING - 1>();      // chunk c complete (<=3 newer pending)
            const int st = c & (RING - 1);

            // consume own 16B per row (conflict-free LDS.128)
            ulonglong2 xv0 = *(const ulonglong2*)(ring + st * STAGEB + 0 * ROWB + lane16);
            ulonglong2 xv1 = *(const ulonglong2*)(ring + st * STAGEB + 1 * ROWB + lane16);
            ulonglong2 xv2 = *(const ulonglong2*)(ring + st * STAGEB + 2 * ROWB + lane16);
            ulonglong2 xv3 = *(const ulonglong2*)(ring + st * STAGEB + 3 * ROWB + lane16);

            // refill stage st with chunk c+4 (memory clobber orders after LDS;
            // async data arrives >=300cyc later, LDS is 29cyc -> WAR safe)
            if (c + RING < 16) {
                #pragma unroll
                for (int r = 0; r < 4; r++)
                    cp_async16(ring_u + st * STAGEB + r * ROWB,
                               xg + (size_t)r * (DIM * 4) + (c + RING) * ROWB + lane16);
            }
            cp_commit();              // empty group for c>=12 keeps accounting

            const int cc = c * 32 + lane;
            #pragma unroll
            for (int e = 0; e < NEXP; e++) {
                ulonglong2 wv = sw2[e * (DIM / 4) + cc];
                ffma2(acc[0][e], xv0.x, wv.x); ffma2(acc[0][e], xv0.y, wv.y);
                ffma2(acc[1][e], xv1.x, wv.x); ffma2(acc[1][e], xv1.y, wv.y);
                ffma2(acc[2][e], xv2.x, wv.x); ffma2(acc[2][e], xv2.y, wv.y);
                ffma2(acc[3][e], xv3.x, wv.x); ffma2(acc[3][e], xv3.y, wv.y);
            }
        }

        // Collapse f32x2 halves, butterfly so lanes 0-3 hold full logits.
        float logit[4][NEXP];
        #pragma unroll
        for (int t = 0; t < 4; t++)
            #pragma unroll
            for (int e = 0; e < NEXP; e++) {
                float v = unpack_sum(acc[t][e]);
                v += __shfl_xor_sync(0xffffffffu, v, 16);
                v += __shfl_xor_sync(0xffffffffu, v, 8);
                v += __shfl_xor_sync(0xffffffffu, v, 4);
                v += __shfl_xor_sync(0xffffffffu, v, 2);
                v += __shfl_xor_sync(0xffffffffu, v, 1);
                logit[t][e] = v;
            }

        if (lane < 4) {
            int token = task * 4 + lane;
            float p[NEXP];
            float m = logit[lane][0];
            #pragma unroll
            for (int e = 1; e < NEXP; e++) m = fmaxf(m, logit[lane][e]);
            float s = 0.0f;
            #pragma unroll
            for (int e = 0; e < NEXP; e++) { p[e] = expf(logit[lane][e] - m); s += p[e]; }
            float inv = 1.0f / s;
            #pragma unroll
            for (int e = 0; e < NEXP; e++) p[e] *= inv;

            // top-2, ties -> lowest index
            int i1 = 0; float b1 = p[0];
            #pragma unroll
            for (int e = 1; e < NEXP; e++) if (p[e] > b1) { b1 = p[e]; i1 = e; }
            int i2 = -1; float b2 = -1.0f;
            #pragma unroll
            for (int e = 0; e < NEXP; e++) if (e != i1 && p[e] > b2) { b2 = p[e]; i2 = e; }

            float ssum = b1 + b2;
            float w1 = b1 / ssum, w2 = b2 / ssum;

            int n0 = token * 2;
            out[n0]     = (float)i1;
            out[n0 + 1] = (float)i2;
            out[NASSIGN + n0]     = w1;
            out[NASSIGN + n0 + 1] = w2;
            out[2 * NASSIGN + 1 + n0]     = 1.0f;
            out[2 * NASSIGN + 1 + n0 + 1] = 1.0f;

            // per-expert bucket append; keys order-independent
            int s1 = atomicAdd(&g_cnt[i1], 1);
            g_bucket[i1][s1] = ((unsigned long long)__float_as_uint(w1) << 32) |
                               (unsigned)(~(unsigned)n0);
            int s2 = atomicAdd(&g_cnt[i2], 1);
            g_bucket[i2][s2] = ((unsigned long long)__float_as_uint(w2) << 32) |
                               (unsigned)(~(unsigned)(n0 + 1));

            #pragma unroll
            for (int e = 0; e < NEXP; e++) atomicAdd(&s_prob[e], p[e]);
        }
        task = next;
    }

    // flush block-accumulated prob sums
    __syncthreads();
    if (tid < NEXP) atomicAdd(&g_probsum[tid], s_prob[tid]);
    __syncthreads();

    // ---- arrival counter: last block finalizes ----
    if (tid == 0) {
        __threadfence();
        unsigned old = atomicAdd(&g_done, 1u);
        s_last = (old == (unsigned)(gridDim.x - 1)) ? 1 : 0;
    }
    __syncthreads();
    if (!s_last) return;

    __shared__ int cnt[NEXP];
    if (tid < NEXP) cnt[tid] = __ldcg(&g_cnt[tid]);
    __syncthreads();

    if (tid == 0) {
        float imp[NEXP], imps = 0.0f;
        #pragma unroll
        for (int e = 0; e < NEXP; e++) { imp[e] = __ldcg(&g_probsum[e]); imps += imp[e]; }
        float loss = 0.0f;
        #pragma unroll
        for (int e = 0; e < NEXP; e++)
            loss += (imp[e] / imps) * ((float)cnt[e] / (float)NASSIGN);
        out[2 * NASSIGN] = (float)NEXP * loss;
    }

    // Capacity drop (rank = #{j: key > key_i}; keep iff rank < CAP). Matches
    // lexsort((-w, expert)) with flat-index tiebreak; rarely triggers
    // (expected per-expert count ~4096 << 5120).
    for (int e = 0; e < NEXP; e++) {
        int c = cnt[e];
        if (c <= CAP) continue;
        for (int i = tid; i < c; i += blockDim.x) {
            unsigned long long ki = __ldcg(&g_bucket[e][i]);
            int rank = 0;
            for (int j = 0; j < c; j++)
                rank += (__ldcg(&g_bucket[e][j]) > ki) ? 1 : 0;
            if (rank >= CAP) {
                unsigned n = ~(unsigned)(ki & 0xffffffffull);
                out[2 * NASSIGN + 1 + n] = 0.0f;
            }
        }
    }
    __syncthreads();

    // reset scratch for the next graph replay
    if (tid < NEXP) { g_cnt[tid] = 0; g_probsum[tid] = 0.0f; }
    if (tid == 0)   { g_done = 0u; g_ticket = 0u; __threadfence(); }
}

extern "C" void kernel_launch(void* const* d_in, const int* in_sizes, int n_in,
                              void* d_out, int out_size) {
    const float* x  = (const float*)d_in[0];
    const float* wg = (const float*)d_in[1];
    float* out = (float*)d_out;
    (void)in_sizes; (void)n_in; (void)out_size;

    cudaFuncSetAttribute(router_main, cudaFuncAttributeMaxDynamicSharedMemorySize,
                         SMEM_DYN);

    router_main<<<NBLK, THREADS, SMEM_DYN>>>(x, wg, out);
}